// round 11
// baseline (speedup 1.0000x reference)
#include <cuda_runtime.h>
#include <cstdint>

#define T_TOK    16384
#define DIM      2048
#define NEXP     64
#define NB       4
#define SEQ      4096
#define BM       64              // tokens per CTA (32 HMMA + 32 FFMA)
#define BK       32              // k per chunk
#define NCHUNK   (DIM / BK)      // 64
#define NTHREADS 256
#define GRID     (T_TOK / BM)    // 256

// ---- stage layout (bytes) ----
// XS4: split-packed X rows 0-31:  32*17 float4 = 8704
// WS4: split-packed W (64 exp):   64*17 float4 = 17408
// XRAW: raw X rows 32-63:         32*36 floats = 4608
// WRAW: raw W transposed [k][e]:  32*68 floats = 8704
#define ROW4     17
#define XS4_OFF  0
#define WS4_OFF  8704
#define XRAW_OFF 26112
#define WRAW_OFF 30720
#define STAGE_B  39424
#define SMEM_BYTES (2 * STAGE_B)          // 78848
// epilogue reuse: red[4][32][68] = 34816 B, sc[64][68] at +34816 (17408 B)

__device__ float        g_score_sum[NB * NEXP];
__device__ unsigned int g_counts[NB * NEXP];
__device__ unsigned int g_done;

__device__ __forceinline__ float2 split2(float x) {
    uint32_t h;
    asm("cvt.rna.tf32.f32 %0, %1;" : "=r"(h) : "f"(x));
    float hf = __uint_as_float(h);
    float r = x - hf;
    uint32_t l;
    asm("cvt.rna.tf32.f32 %0, %1;" : "=r"(l) : "f"(r));
    return make_float2(hf, __uint_as_float(l));
}

__device__ __forceinline__ void mma_tf32(float* c,
                                         float a0, float a1, float a2, float a3,
                                         float b0, float b1) {
    asm volatile(
        "mma.sync.aligned.m16n8k8.row.col.f32.tf32.tf32.f32 "
        "{%0,%1,%2,%3}, {%4,%5,%6,%7}, {%8,%9}, {%0,%1,%2,%3};"
        : "+f"(c[0]), "+f"(c[1]), "+f"(c[2]), "+f"(c[3])
        : "r"(__float_as_uint(a0)), "r"(__float_as_uint(a1)),
          "r"(__float_as_uint(a2)), "r"(__float_as_uint(a3)),
          "r"(__float_as_uint(b0)), "r"(__float_as_uint(b1)));
}

__device__ __forceinline__ void split_pack4(float4* dst4, int base,
                                            float4 f0, float4 f1) {
    float xv[8] = { f0.x, f0.y, f0.z, f0.w, f1.x, f1.y, f1.z, f1.w };
    float2 s[8];
#pragma unroll
    for (int j = 0; j < 8; j++) s[j] = split2(xv[j]);
#pragma unroll
    for (int t = 0; t < 4; t++)
        dst4[base + t] = make_float4(s[t].x, s[t].y, s[t + 4].x, s[t + 4].y);
}

__device__ __forceinline__ void ffma8(float* acc, float a, float4 b0, float4 b1) {
    acc[0] += a * b0.x; acc[1] += a * b0.y; acc[2] += a * b0.z; acc[3] += a * b0.w;
    acc[4] += a * b1.x; acc[5] += a * b1.y; acc[6] += a * b1.z; acc[7] += a * b1.w;
}

__global__ __launch_bounds__(NTHREADS, 2)
void moe_gate_hyb(const float* __restrict__ X,
                  const float* __restrict__ W,
                  float* __restrict__ out)
{
    extern __shared__ char smem[];
    __shared__ unsigned int cnt[NEXP];
    __shared__ int last_flag;

    const int tid  = threadIdx.x;
    const int wid  = tid >> 5;
    const int lane = tid & 31;
    const int tok0 = blockIdx.x * BM;

    // ---- staging geometry ----
    // warps 4-7 stage split rows 0-31 (HMMA data), warps 0-3 stage raw rows 32-63
    const int srow = ((tid + 128) & 255) >> 2;   // 0..63
    const int as   = tid & 3;                    // k-group of 8
    const int wrow = tid >> 2;                   // W expert row 0..63

    const float* Xp = X + (size_t)(tok0 + srow) * DIM + as * 8;
    const float* Wp = W + (size_t)wrow * DIM + as * 8;

    // ---- HMMA consumer constants (warps 4-7) ----
    const int g  = lane >> 2;
    const int tg = lane & 3;
    const int ks = wid - 4;                      // k8-slice (valid for wid>=4)
    const int aoff = g * ROW4 + ks * 4 + tg;     // XS4 float4 idx
    const int boff = g * ROW4 + ks * 4 + tg;     // WS4 float4 idx

    // ---- FFMA consumer constants (warps 0-3) ----
    const int tl = lane >> 3;                    // 0..3
    const int eg = lane & 7;                     // 0..7
    const int t0 = wid * 8 + 2 * tl;             // local FFMA token 0..31 (rows 32+t0)

    // accumulators (union of both paths; only one used per warp)
    float acc[2][8][4];     // HMMA: [mf][nt][4]
#pragma unroll
    for (int a = 0; a < 2; a++)
#pragma unroll
        for (int b = 0; b < 8; b++)
#pragma unroll
            for (int c = 0; c < 4; c++) acc[a][b][c] = 0.0f;
    float facc[2][8];       // FFMA: [token][expert]
#pragma unroll
    for (int a = 0; a < 2; a++)
#pragma unroll
        for (int b = 0; b < 8; b++) facc[a][b] = 0.0f;

    float4 xa0, xa1, xw0, xw1;

    // ---- prolog: load + stage chunk 0 ----
    xa0 = *(const float4*)Xp;  xa1 = *(const float4*)(Xp + 4);
    xw0 = *(const float4*)Wp;  xw1 = *(const float4*)(Wp + 4);
    {
        char* stg = smem;
        if (srow < 32) {
            split_pack4((float4*)(stg + XS4_OFF), srow * ROW4 + as * 4, xa0, xa1);
        } else {
            float4* xr = (float4*)(stg + XRAW_OFF);
            xr[(srow - 32) * 9 + as * 2]     = xa0;
            xr[(srow - 32) * 9 + as * 2 + 1] = xa1;
        }
        split_pack4((float4*)(stg + WS4_OFF), wrow * ROW4 + as * 4, xw0, xw1);
        float* wr = (float*)(stg + WRAW_OFF);
        float wv[8] = { xw0.x, xw0.y, xw0.z, xw0.w, xw1.x, xw1.y, xw1.z, xw1.w };
#pragma unroll
        for (int j = 0; j < 8; j++) wr[(as * 8 + j) * 68 + wrow] = wv[j];
    }
    if (tid < NEXP) cnt[tid] = 0u;
    __syncthreads();

    for (int kt = 0; kt < NCHUNK; kt++) {
        char* stg = smem + (kt & 1) * STAGE_B;

        // ---- prefetch next chunk ----
        if (kt + 1 < NCHUNK) {
            Xp += BK; Wp += BK;
            xa0 = *(const float4*)Xp;  xa1 = *(const float4*)(Xp + 4);
            xw0 = *(const float4*)Wp;  xw1 = *(const float4*)(Wp + 4);
        }

        if (wid >= 4) {
            // ======== HMMA path: m32 x n64 x (k8 slice ks) ========
            const float4* A4 = (const float4*)(stg + XS4_OFF);
            const float4* B4 = (const float4*)(stg + WS4_OFF);
            float4 ar0 = A4[aoff];
            float4 ar1 = A4[aoff + 8  * ROW4];
            float4 ar2 = A4[aoff + 16 * ROW4];
            float4 ar3 = A4[aoff + 24 * ROW4];
#pragma unroll
            for (int ntp = 0; ntp < 4; ntp++) {
                float4 b0 = B4[boff + (2 * ntp)     * 8 * ROW4];
                float4 b1 = B4[boff + (2 * ntp + 1) * 8 * ROW4];
                float* c00 = acc[0][2 * ntp];
                float* c10 = acc[1][2 * ntp];
                float* c01 = acc[0][2 * ntp + 1];
                float* c11 = acc[1][2 * ntp + 1];
                mma_tf32(c00, ar0.x, ar1.x, ar0.z, ar1.z, b0.x, b0.z);
                mma_tf32(c10, ar2.x, ar3.x, ar2.z, ar3.z, b0.x, b0.z);
                mma_tf32(c01, ar0.x, ar1.x, ar0.z, ar1.z, b1.x, b1.z);
                mma_tf32(c11, ar2.x, ar3.x, ar2.z, ar3.z, b1.x, b1.z);
                mma_tf32(c00, ar0.x, ar1.x, ar0.z, ar1.z, b0.y, b0.w);
                mma_tf32(c10, ar2.x, ar3.x, ar2.z, ar3.z, b0.y, b0.w);
                mma_tf32(c01, ar0.x, ar1.x, ar0.z, ar1.z, b1.y, b1.w);
                mma_tf32(c11, ar2.x, ar3.x, ar2.z, ar3.z, b1.y, b1.w);
                mma_tf32(c00, ar0.y, ar1.y, ar0.w, ar1.w, b0.x, b0.z);
                mma_tf32(c10, ar2.y, ar3.y, ar2.w, ar3.w, b0.x, b0.z);
                mma_tf32(c01, ar0.y, ar1.y, ar0.w, ar1.w, b1.x, b1.z);
                mma_tf32(c11, ar2.y, ar3.y, ar2.w, ar3.w, b1.x, b1.z);
                mma_tf32(c00, ar0.y, ar1.y, ar0.w, ar1.w, b0.y, b0.w);
                mma_tf32(c10, ar2.y, ar3.y, ar2.w, ar3.w, b0.y, b0.w);
                mma_tf32(c01, ar0.y, ar1.y, ar0.w, ar1.w, b1.y, b1.w);
                mma_tf32(c11, ar2.y, ar3.y, ar2.w, ar3.w, b1.y, b1.w);
            }
        } else {
            // ======== FFMA path: 2 tokens x 64 experts x k32 ========
            const float4* XR = (const float4*)(stg + XRAW_OFF);
            const float4* WR = (const float4*)(stg + WRAW_OFF);
#pragma unroll
            for (int kk4 = 0; kk4 < 8; kk4++) {
                float4 a0 = XR[t0 * 9 + kk4];
                float4 a1 = XR[(t0 + 1) * 9 + kk4];
#pragma unroll
                for (int j = 0; j < 4; j++) {
                    float4 b0 = WR[(kk4 * 4 + j) * ROW4 + eg * 2];
                    float4 b1 = WR[(kk4 * 4 + j) * ROW4 + eg * 2 + 1];
                    float av = (j == 0) ? a0.x : (j == 1) ? a0.y : (j == 2) ? a0.z : a0.w;
                    float aw = (j == 0) ? a1.x : (j == 1) ? a1.y : (j == 2) ? a1.z : a1.w;
                    ffma8(facc[0], av, b0, b1);
                    ffma8(facc[1], aw, b0, b1);
                }
            }
        }

        // ---- stage prefetched regs into other buffer ----
        if (kt + 1 < NCHUNK) {
            char* nstg = smem + ((kt + 1) & 1) * STAGE_B;
            if (srow < 32) {
                split_pack4((float4*)(nstg + XS4_OFF), srow * ROW4 + as * 4, xa0, xa1);
            } else {
                float4* xr = (float4*)(nstg + XRAW_OFF);
                xr[(srow - 32) * 9 + as * 2]     = xa0;
                xr[(srow - 32) * 9 + as * 2 + 1] = xa1;
            }
            split_pack4((float4*)(nstg + WS4_OFF), wrow * ROW4 + as * 4, xw0, xw1);
            float* wr = (float*)(nstg + WRAW_OFF);
            float wv[8] = { xw0.x, xw0.y, xw0.z, xw0.w, xw1.x, xw1.y, xw1.z, xw1.w };
#pragma unroll
            for (int j = 0; j < 8; j++) wr[(as * 8 + j) * 68 + wrow] = wv[j];
        }
        __syncthreads();
    }

    // ---- writeback ----
    float* red = (float*)smem;                       // [4][32][68] (HMMA slices)
    float* sc  = (float*)(smem + 34816);             // [64][68]
    if (wid >= 4) {
#pragma unroll
        for (int mf = 0; mf < 2; mf++) {
            const int row = mf * 16 + g;
#pragma unroll
            for (int nt = 0; nt < 8; nt++) {
                const int e = nt * 8 + 2 * tg;
                *(float2*)&red[(ks * 32 + row) * 68 + e] =
                    make_float2(acc[mf][nt][0], acc[mf][nt][1]);
                *(float2*)&red[(ks * 32 + row + 8) * 68 + e] =
                    make_float2(acc[mf][nt][2], acc[mf][nt][3]);
            }
        }
    } else {
        // FFMA scores -> sc rows 32+t0, 32+t0+1
        *(float4*)&sc[(32 + t0) * 68 + eg * 8]     = make_float4(facc[0][0], facc[0][1], facc[0][2], facc[0][3]);
        *(float4*)&sc[(32 + t0) * 68 + eg * 8 + 4] = make_float4(facc[0][4], facc[0][5], facc[0][6], facc[0][7]);
        *(float4*)&sc[(33 + t0) * 68 + eg * 8]     = make_float4(facc[1][0], facc[1][1], facc[1][2], facc[1][3]);
        *(float4*)&sc[(33 + t0) * 68 + eg * 8 + 4] = make_float4(facc[1][4], facc[1][5], facc[1][6], facc[1][7]);
    }
    __syncthreads();

    // reduce 4 HMMA k-slices into sc rows 0-31
    for (int i = tid; i < 32 * NEXP; i += NTHREADS) {
        const int t = i >> 6, e = i & 63;
        sc[t * 68 + e] = red[(0 * 32 + t) * 68 + e]
                       + red[(1 * 32 + t) * 68 + e]
                       + red[(2 * 32 + t) * 68 + e]
                       + red[(3 * 32 + t) * 68 + e];
    }
    __syncthreads();

    // ---- per-token softmax + top-2 ----
    if (tid < BM) {
        float v[64];
#pragma unroll
        for (int e = 0; e < NEXP; e++) v[e] = sc[tid * 68 + e];
        float mx = v[0];
#pragma unroll
        for (int e = 1; e < NEXP; e++) mx = fmaxf(mx, v[e]);
        float sum = 0.0f;
#pragma unroll
        for (int e = 0; e < NEXP; e++) { v[e] = expf(v[e] - mx); sum += v[e]; }
        float inv = 1.0f / sum;

        float v1 = -1.0f, v2 = -1.0f;
        int i1 = 0, i2 = 0;
#pragma unroll
        for (int e = 0; e < NEXP; e++) {
            float p = v[e] * inv;
            sc[tid * 68 + e] = p;
            if (p > v1) { v2 = v1; i2 = i1; v1 = p; i1 = e; }
            else if (p > v2) { v2 = p; i2 = e; }
        }
        float tot = v1 + v2 + 1e-20f;
        const int gt = tok0 + tid;
        out[2 * gt + 0] = (float)i1;
        out[2 * gt + 1] = (float)i2;
        out[2 * T_TOK + 2 * gt + 0] = v1 / tot;
        out[2 * T_TOK + 2 * gt + 1] = v2 / tot;

        atomicAdd(&cnt[i1], 1u);
        atomicAdd(&cnt[i2], 1u);
    }
    __syncthreads();

    // ---- per-expert sums -> global ----
    if (tid < NEXP) {
        float cs = 0.0f;
#pragma unroll 8
        for (int t = 0; t < BM; t++) cs += sc[t * 68 + tid];
        const int b = tok0 / SEQ;
        atomicAdd(&g_score_sum[b * NEXP + tid], cs);
        atomicAdd(&g_counts[b * NEXP + tid], cnt[tid]);
    }

    // ---- last-block finalize (aux loss) ----
    __threadfence();
    __syncthreads();
    if (tid == 0) {
        unsigned int v = atomicAdd(&g_done, 1u);
        last_flag = (v == (unsigned int)(GRID - 1));
    }
    __syncthreads();
    if (last_flag) {
        float* redf = (float*)smem;   // 256 floats
        const int i = tid;            // 256 = NB*NEXP
        float sv = *((volatile float*)&g_score_sum[i]);
        unsigned int cv = *((volatile unsigned int*)&g_counts[i]);
        float v = (float)cv * ((float)NEXP / (float)(SEQ * 2)) * (sv / (float)SEQ);
        g_score_sum[i] = 0.0f;
        g_counts[i] = 0u;
        if (tid == 0) g_done = 0u;
        redf[i] = v;
        __syncthreads();
        for (int s = (NB * NEXP) / 2; s > 0; s >>= 1) {
            if (i < s) redf[i] += redf[i + s];
            __syncthreads();
        }
        if (i == 0) out[4 * T_TOK] = redf[0] * (0.1f / (float)NB);
    }
}

extern "C" void kernel_launch(void* const* d_in, const int* in_sizes, int n_in,
                              void* d_out, int out_size) {
    const float* X = (const float*)d_in[0];   // [4,4096,2048] f32
    const float* W = (const float*)d_in[1];   // [64,2048] f32
    float* out = (float*)d_out;

    cudaFuncSetAttribute(moe_gate_hyb, cudaFuncAttributeMaxDynamicSharedMemorySize, SMEM_BYTES);
    moe_gate_hyb<<<GRID, NTHREADS, SMEM_BYTES>>>(X, W, out);
}

// round 12
// speedup vs baseline: 1.4490x; 1.4490x over previous
#include <cuda_runtime.h>
#include <cstdint>

#define T_TOK    16384
#define DIM      2048
#define NEXP     64
#define NB       4
#define SEQ      4096
#define BM       64              // tokens per CTA: rows 0-31 HMMA, 32-63 FFMA
#define BK       32
#define NCHUNK   (DIM / BK)      // 64
#define NTHREADS 256
#define GRID     (T_TOK / BM)    // 256

// ---- stage layout (bytes) ----
#define ROW4     17
#define XS4_OFF  0               // split-packed X rows 0-31: 32*17 float4 = 8704
#define WS4_OFF  8704            // split-packed W:           64*17 float4 = 17408
#define AT_OFF   26112           // raw X^T rows 32-63: [32k][36] f32 = 4608
#define BT_OFF   30720           // raw W^T:            [32k][68] f32 = 8704
#define STAGE_B  39424
#define SMEM_BYTES (2 * STAGE_B)  // 78848
// epilogue: red[4][32][68] @0 (34816 B), sc[64][68] @34816 (17408 B)

__device__ float        g_score_sum[NB * NEXP];
__device__ unsigned int g_counts[NB * NEXP];
__device__ unsigned int g_done;

__device__ __forceinline__ float2 split2(float x) {
    uint32_t h;
    asm("cvt.rna.tf32.f32 %0, %1;" : "=r"(h) : "f"(x));
    float hf = __uint_as_float(h);
    float r = x - hf;
    uint32_t l;
    asm("cvt.rna.tf32.f32 %0, %1;" : "=r"(l) : "f"(r));
    return make_float2(hf, __uint_as_float(l));
}

__device__ __forceinline__ void mma_tf32(float* c,
                                         float a0, float a1, float a2, float a3,
                                         float b0, float b1) {
    asm volatile(
        "mma.sync.aligned.m16n8k8.row.col.f32.tf32.tf32.f32 "
        "{%0,%1,%2,%3}, {%4,%5,%6,%7}, {%8,%9}, {%0,%1,%2,%3};"
        : "+f"(c[0]), "+f"(c[1]), "+f"(c[2]), "+f"(c[3])
        : "r"(__float_as_uint(a0)), "r"(__float_as_uint(a1)),
          "r"(__float_as_uint(a2)), "r"(__float_as_uint(a3)),
          "r"(__float_as_uint(b0)), "r"(__float_as_uint(b1)));
}

__device__ __forceinline__ void split_pack4(float4* dst4, int base,
                                            float4 f0, float4 f1) {
    float xv[8] = { f0.x, f0.y, f0.z, f0.w, f1.x, f1.y, f1.z, f1.w };
    float2 s[8];
#pragma unroll
    for (int j = 0; j < 8; j++) s[j] = split2(xv[j]);
#pragma unroll
    for (int t = 0; t < 4; t++)
        dst4[base + t] = make_float4(s[t].x, s[t].y, s[t + 4].x, s[t + 4].y);
}

__global__ __launch_bounds__(NTHREADS, 2)
void moe_gate_hyb2(const float* __restrict__ X,
                   const float* __restrict__ W,
                   float* __restrict__ out)
{
    extern __shared__ char smem[];
    __shared__ unsigned int cnt[NEXP];
    __shared__ int last_flag;

    const int tid  = threadIdx.x;
    const int wid  = tid >> 5;
    const int lane = tid & 31;
    const int tok0 = blockIdx.x * BM;

    // ---- staging geometry: warps 4-7 own X rows 0-31 (split), 0-3 own 32-63 (raw) ----
    const int srow = ((tid + 128) & 255) >> 2;   // 0..63
    const int as   = tid & 3;                    // k-group of 8
    const int wrow = tid >> 2;                   // W expert 0..63

    const float* Xp = X + (size_t)(tok0 + srow) * DIM + as * 8;
    const float* Wp = W + (size_t)wrow * DIM + as * 8;

    // ---- HMMA consumer constants (warps 4-7) ----
    const int g  = lane >> 2;
    const int tg = lane & 3;
    const int ks = wid - 4;
    const int aoff = g * ROW4 + ks * 4 + tg;
    const int boff = g * ROW4 + ks * 4 + tg;

    // ---- FFMA consumer constants (warps 0-3): 4 tok x 4 exp per thread ----
    const int tx  = lane & 15;                   // expert quad 0..15
    const int tyq = wid * 2 + (lane >> 4);       // token quad 0..7 (tokens 32+tyq*4..)

    float acc[2][8][4];      // HMMA accum
#pragma unroll
    for (int a = 0; a < 2; a++)
#pragma unroll
        for (int b = 0; b < 8; b++)
#pragma unroll
            for (int c = 0; c < 4; c++) acc[a][b][c] = 0.0f;
    float facc[4][4];        // FFMA accum [tok][exp]
#pragma unroll
    for (int a = 0; a < 4; a++)
#pragma unroll
        for (int b = 0; b < 4; b++) facc[a][b] = 0.0f;

    float4 xa0, xa1, xw0, xw1;

    // ---- prolog: load + stage chunk 0 ----
    xa0 = *(const float4*)Xp;  xa1 = *(const float4*)(Xp + 4);
    xw0 = *(const float4*)Wp;  xw1 = *(const float4*)(Wp + 4);
    {
        char* stg = smem;
        if (srow < 32) {
            split_pack4((float4*)(stg + XS4_OFF), srow * ROW4 + as * 4, xa0, xa1);
        } else {
            float* AT = (float*)(stg + AT_OFF);
            float xv[8] = { xa0.x, xa0.y, xa0.z, xa0.w, xa1.x, xa1.y, xa1.z, xa1.w };
            const int ft = srow - 32;
#pragma unroll
            for (int j = 0; j < 8; j++) AT[(as * 8 + j) * 36 + ft] = xv[j];
        }
        split_pack4((float4*)(stg + WS4_OFF), wrow * ROW4 + as * 4, xw0, xw1);
        float* BT = (float*)(stg + BT_OFF);
        float wv[8] = { xw0.x, xw0.y, xw0.z, xw0.w, xw1.x, xw1.y, xw1.z, xw1.w };
#pragma unroll
        for (int j = 0; j < 8; j++) BT[(as * 8 + j) * 68 + wrow] = wv[j];
    }
    if (tid < NEXP) cnt[tid] = 0u;
    __syncthreads();

    for (int kt = 0; kt < NCHUNK; kt++) {
        char* stg = smem + (kt & 1) * STAGE_B;

        // ---- prefetch next chunk ----
        if (kt + 1 < NCHUNK) {
            Xp += BK; Wp += BK;
            xa0 = *(const float4*)Xp;  xa1 = *(const float4*)(Xp + 4);
            xw0 = *(const float4*)Wp;  xw1 = *(const float4*)(Wp + 4);
        }

        if (wid >= 4) {
            // ======== HMMA: tokens 0-31, m32 x n64 x k8-slice ========
            const float4* A4 = (const float4*)(stg + XS4_OFF);
            const float4* B4 = (const float4*)(stg + WS4_OFF);
            float4 ar0 = A4[aoff];
            float4 ar1 = A4[aoff + 8  * ROW4];
            float4 ar2 = A4[aoff + 16 * ROW4];
            float4 ar3 = A4[aoff + 24 * ROW4];
#pragma unroll
            for (int ntp = 0; ntp < 4; ntp++) {
                float4 b0 = B4[boff + (2 * ntp)     * 8 * ROW4];
                float4 b1 = B4[boff + (2 * ntp + 1) * 8 * ROW4];
                float* c00 = acc[0][2 * ntp];
                float* c10 = acc[1][2 * ntp];
                float* c01 = acc[0][2 * ntp + 1];
                float* c11 = acc[1][2 * ntp + 1];
                mma_tf32(c00, ar0.x, ar1.x, ar0.z, ar1.z, b0.x, b0.z);
                mma_tf32(c10, ar2.x, ar3.x, ar2.z, ar3.z, b0.x, b0.z);
                mma_tf32(c01, ar0.x, ar1.x, ar0.z, ar1.z, b1.x, b1.z);
                mma_tf32(c11, ar2.x, ar3.x, ar2.z, ar3.z, b1.x, b1.z);
                mma_tf32(c00, ar0.x, ar1.x, ar0.z, ar1.z, b0.y, b0.w);
                mma_tf32(c10, ar2.x, ar3.x, ar2.z, ar3.z, b0.y, b0.w);
                mma_tf32(c01, ar0.x, ar1.x, ar0.z, ar1.z, b1.y, b1.w);
                mma_tf32(c11, ar2.x, ar3.x, ar2.z, ar3.z, b1.y, b1.w);
                mma_tf32(c00, ar0.y, ar1.y, ar0.w, ar1.w, b0.x, b0.z);
                mma_tf32(c10, ar2.y, ar3.y, ar2.w, ar3.w, b0.x, b0.z);
                mma_tf32(c01, ar0.y, ar1.y, ar0.w, ar1.w, b1.x, b1.z);
                mma_tf32(c11, ar2.y, ar3.y, ar2.w, ar3.w, b1.x, b1.z);
                mma_tf32(c00, ar0.y, ar1.y, ar0.w, ar1.w, b0.y, b0.w);
                mma_tf32(c10, ar2.y, ar3.y, ar2.w, ar3.w, b0.y, b0.w);
                mma_tf32(c01, ar0.y, ar1.y, ar0.w, ar1.w, b1.y, b1.w);
                mma_tf32(c11, ar2.y, ar3.y, ar2.w, ar3.w, b1.y, b1.w);
            }
        } else {
            // ======== FFMA: tokens 32-63, 4 tok x 4 exp per thread, full k32 ========
            const float* AT = (const float*)(stg + AT_OFF);
            const float* BT = (const float*)(stg + BT_OFF);
#pragma unroll 8
            for (int k = 0; k < BK; k++) {
                float4 a4 = *(const float4*)&AT[k * 36 + tyq * 4];
                float4 b4 = *(const float4*)&BT[k * 68 + tx * 4];
                float av[4] = { a4.x, a4.y, a4.z, a4.w };
                float bv[4] = { b4.x, b4.y, b4.z, b4.w };
#pragma unroll
                for (int i = 0; i < 4; i++)
#pragma unroll
                    for (int j = 0; j < 4; j++)
                        facc[i][j] += av[i] * bv[j];
            }
        }

        // ---- stage prefetched regs into other buffer ----
        if (kt + 1 < NCHUNK) {
            char* nstg = smem + ((kt + 1) & 1) * STAGE_B;
            if (srow < 32) {
                split_pack4((float4*)(nstg + XS4_OFF), srow * ROW4 + as * 4, xa0, xa1);
            } else {
                float* AT = (float*)(nstg + AT_OFF);
                float xv[8] = { xa0.x, xa0.y, xa0.z, xa0.w, xa1.x, xa1.y, xa1.z, xa1.w };
                const int ft = srow - 32;
#pragma unroll
                for (int j = 0; j < 8; j++) AT[(as * 8 + j) * 36 + ft] = xv[j];
            }
            split_pack4((float4*)(nstg + WS4_OFF), wrow * ROW4 + as * 4, xw0, xw1);
            float* BT = (float*)(nstg + BT_OFF);
            float wv[8] = { xw0.x, xw0.y, xw0.z, xw0.w, xw1.x, xw1.y, xw1.z, xw1.w };
#pragma unroll
            for (int j = 0; j < 8; j++) BT[(as * 8 + j) * 68 + wrow] = wv[j];
        }
        __syncthreads();
    }

    // ---- writeback ----
    float* red = (float*)smem;                       // [4][32][68] HMMA k-slices
    float* sc  = (float*)(smem + 34816);             // [64][68]
    if (wid >= 4) {
#pragma unroll
        for (int mf = 0; mf < 2; mf++) {
            const int row = mf * 16 + g;
#pragma unroll
            for (int nt = 0; nt < 8; nt++) {
                const int e = nt * 8 + 2 * tg;
                *(float2*)&red[(ks * 32 + row) * 68 + e] =
                    make_float2(acc[mf][nt][0], acc[mf][nt][1]);
                *(float2*)&red[(ks * 32 + row + 8) * 68 + e] =
                    make_float2(acc[mf][nt][2], acc[mf][nt][3]);
            }
        }
    } else {
#pragma unroll
        for (int t = 0; t < 4; t++)
            *(float4*)&sc[(32 + tyq * 4 + t) * 68 + tx * 4] =
                make_float4(facc[t][0], facc[t][1], facc[t][2], facc[t][3]);
    }
    __syncthreads();

    // reduce 4 HMMA k-slices into sc rows 0-31
    for (int i = tid; i < 32 * NEXP; i += NTHREADS) {
        const int t = i >> 6, e = i & 63;
        sc[t * 68 + e] = red[(0 * 32 + t) * 68 + e]
                       + red[(1 * 32 + t) * 68 + e]
                       + red[(2 * 32 + t) * 68 + e]
                       + red[(3 * 32 + t) * 68 + e];
    }
    __syncthreads();

    // ---- per-token softmax + top-2 ----
    if (tid < BM) {
        float v[64];
#pragma unroll
        for (int e = 0; e < NEXP; e++) v[e] = sc[tid * 68 + e];
        float mx = v[0];
#pragma unroll
        for (int e = 1; e < NEXP; e++) mx = fmaxf(mx, v[e]);
        float sum = 0.0f;
#pragma unroll
        for (int e = 0; e < NEXP; e++) { v[e] = expf(v[e] - mx); sum += v[e]; }
        float inv = 1.0f / sum;

        float v1 = -1.0f, v2 = -1.0f;
        int i1 = 0, i2 = 0;
#pragma unroll
        for (int e = 0; e < NEXP; e++) {
            float p = v[e] * inv;
            sc[tid * 68 + e] = p;
            if (p > v1) { v2 = v1; i2 = i1; v1 = p; i1 = e; }
            else if (p > v2) { v2 = p; i2 = e; }
        }
        float tot = v1 + v2 + 1e-20f;
        const int gt = tok0 + tid;
        out[2 * gt + 0] = (float)i1;
        out[2 * gt + 1] = (float)i2;
        out[2 * T_TOK + 2 * gt + 0] = v1 / tot;
        out[2 * T_TOK + 2 * gt + 1] = v2 / tot;

        atomicAdd(&cnt[i1], 1u);
        atomicAdd(&cnt[i2], 1u);
    }
    __syncthreads();

    // ---- per-expert sums -> global ----
    if (tid < NEXP) {
        float cs = 0.0f;
#pragma unroll 8
        for (int t = 0; t < BM; t++) cs += sc[t * 68 + tid];
        const int b = tok0 / SEQ;
        atomicAdd(&g_score_sum[b * NEXP + tid], cs);
        atomicAdd(&g_counts[b * NEXP + tid], cnt[tid]);
    }

    // ---- last-block finalize (aux loss) ----
    __threadfence();
    __syncthreads();
    if (tid == 0) {
        unsigned int v = atomicAdd(&g_done, 1u);
        last_flag = (v == (unsigned int)(GRID - 1));
    }
    __syncthreads();
    if (last_flag) {
        float* redf = (float*)smem;
        const int i = tid;            // 256 = NB*NEXP
        float sv = *((volatile float*)&g_score_sum[i]);
        unsigned int cv = *((volatile unsigned int*)&g_counts[i]);
        float v = (float)cv * ((float)NEXP / (float)(SEQ * 2)) * (sv / (float)SEQ);
        g_score_sum[i] = 0.0f;
        g_counts[i] = 0u;
        if (tid == 0) g_done = 0u;
        redf[i] = v;
        __syncthreads();
        for (int s = (NB * NEXP) / 2; s > 0; s >>= 1) {
            if (i < s) redf[i] += redf[i + s];
            __syncthreads();
        }
        if (i == 0) out[4 * T_TOK] = redf[0] * (0.1f / (float)NB);
    }
}

extern "C" void kernel_launch(void* const* d_in, const int* in_sizes, int n_in,
                              void* d_out, int out_size) {
    const float* X = (const float*)d_in[0];   // [4,4096,2048] f32
    const float* W = (const float*)d_in[1];   // [64,2048] f32
    float* out = (float*)d_out;

    cudaFuncSetAttribute(moe_gate_hyb2, cudaFuncAttributeMaxDynamicSharedMemorySize, SMEM_BYTES);
    moe_gate_hyb2<<<GRID, NTHREADS, SMEM_BYTES>>>(X, W, out);
}

// round 14
// speedup vs baseline: 4.2126x; 2.9072x over previous
#include <cuda_runtime.h>
#include <cuda_fp16.h>
#include <cstdint>

#define T_TOK    16384
#define DIM      2048
#define NEXP     64
#define NB       4
#define SEQ      4096
#define BM       64              // tokens per CTA
#define BK       32              // k per chunk (2 x k16 blocks)
#define NCHUNK   (DIM / BK)      // 64
#define NTHREADS 256
#define GRID     (T_TOK / BM)    // 256
#define NKB      (DIM / 16)      // 128 k16-blocks

#define WSCALE   1024.0f         // exact pow2: W residual -> fp16 normal range
#define XSCALE   256.0f          // exact pow2: X residual -> fp16 normal range
#define UNSCALE  (1.0f / (WSCALE * XSCALE))   // 2^-18, exact

// smem: W stages 2 x 8192 B during loop; epilogue red[128][68] f32 = 34816 B
#define WSTAGE_B 8192
#define SMEM_BYTES 34816

// Pre-split W (scaled) in fragment-native layout: [kb][e][tg] -> 16B block
//   .x = h1(k=2tg,2tg+1) | .y = h1(k=2tg+8,2tg+9) | .z,.w = h2 same cols
__device__ uint4    g_wfrag[NKB * NEXP * 4];      // 512 KB
__device__ float    g_score_sum[NB * NEXP];
__device__ unsigned g_counts[NB * NEXP];
__device__ unsigned g_done;

__device__ __forceinline__ void split_pair(float x0, float x1,
                                           uint32_t& p1, uint32_t& p2) {
    __half2 h1 = __floats2half2_rn(x0, x1);       // lo = x0, hi = x1
    float2  f  = __half22float2(h1);
    __half2 h2 = __floats2half2_rn(x0 - f.x, x1 - f.y);
    p1 = *reinterpret_cast<uint32_t*>(&h1);
    p2 = *reinterpret_cast<uint32_t*>(&h2);
}

__device__ __forceinline__ void mma_f16(float* c,
                                        uint32_t a0, uint32_t a1, uint32_t a2, uint32_t a3,
                                        uint32_t b0, uint32_t b1) {
    asm volatile(
        "mma.sync.aligned.m16n8k16.row.col.f32.f16.f16.f32 "
        "{%0,%1,%2,%3}, {%4,%5,%6,%7}, {%8,%9}, {%0,%1,%2,%3};"
        : "+f"(c[0]), "+f"(c[1]), "+f"(c[2]), "+f"(c[3])
        : "r"(a0), "r"(a1), "r"(a2), "r"(a3), "r"(b0), "r"(b1));
}

// ---- pre-kernel: split scaled W once into fragment-native layout ----
__global__ void presplit_w_kernel(const float* __restrict__ W) {
    int idx = blockIdx.x * 256 + threadIdx.x;     // 0..32767
    int tg = idx & 3;
    int e  = (idx >> 2) & 63;
    int kb = idx >> 8;
    const float* src = W + (size_t)e * DIM + kb * 16;
    float2 lo = *(const float2*)(src + 2 * tg);
    float2 hi = *(const float2*)(src + 2 * tg + 8);
    uint32_t w0, w1, w2, w3;
    split_pair(lo.x * WSCALE, lo.y * WSCALE, w0, w2);
    split_pair(hi.x * WSCALE, hi.y * WSCALE, w1, w3);
    g_wfrag[idx] = make_uint4(w0, w1, w2, w3);
}

__global__ __launch_bounds__(NTHREADS, 2)
void moe_gate_f16(const float* __restrict__ X,
                  float* __restrict__ out)
{
    extern __shared__ char smem[];
    __shared__ unsigned int cnt[NEXP];
    __shared__ int last_flag;

    const int tid  = threadIdx.x;
    const int wid  = tid >> 5;
    const int lane = tid & 31;
    const int g    = lane >> 2;       // 0..7
    const int tg   = lane & 3;        // 0..3
    const int tgp  = wid >> 1;        // token group 0..3 (16 tokens each)
    const int ksl  = wid & 1;         // k16-slice within k32 chunk
    const int tok0 = blockIdx.x * BM;
    const int row0 = tgp * 16 + g;    // this thread's m-row (and row0+8)

    // X gmem pointers: pairs at k = kt*32 + ksl*16 + {2tg, 2tg+8}
    const float* Xr0 = X + (size_t)(tok0 + row0) * DIM + ksl * 16 + 2 * tg;
    const float* Xr1 = Xr0 + 8 * DIM;

    // consumer B offset within a stage (bytes): ksl*4096 + e*64 + tg*16
    const int boff = ksl * 4096 + g * 64 + tg * 16;

    float acc[8][4];
#pragma unroll
    for (int nt = 0; nt < 8; nt++)
#pragma unroll
        for (int i = 0; i < 4; i++) acc[nt][i] = 0.0f;

    // ---- prolog: chunk 0 ----
    float2 ra0 = *(const float2*)(Xr0);
    float2 ra2 = *(const float2*)(Xr0 + 8);
    float2 ra1 = *(const float2*)(Xr1);
    float2 ra3 = *(const float2*)(Xr1 + 8);
    uint4 wn0 = g_wfrag[tid];
    uint4 wn1 = g_wfrag[tid + 256];
    ((uint4*)smem)[tid]       = wn0;
    ((uint4*)smem)[tid + 256] = wn1;
    if (tid < NEXP) cnt[tid] = 0u;
    __syncthreads();

    for (int kt = 0; kt < NCHUNK; kt++) {
        const int stage = kt & 1;

        // split current (scaled) A into fragments
        uint32_t ah1[4], ah2[4];
        split_pair(ra0.x * XSCALE, ra0.y * XSCALE, ah1[0], ah2[0]);
        split_pair(ra1.x * XSCALE, ra1.y * XSCALE, ah1[1], ah2[1]);
        split_pair(ra2.x * XSCALE, ra2.y * XSCALE, ah1[2], ah2[2]);
        split_pair(ra3.x * XSCALE, ra3.y * XSCALE, ah1[3], ah2[3]);

        // prefetch next chunk (A raw + W frags)
        if (kt + 1 < NCHUNK) {
            const float* xn0 = Xr0 + (kt + 1) * BK;
            const float* xn1 = Xr1 + (kt + 1) * BK;
            ra0 = *(const float2*)(xn0);
            ra2 = *(const float2*)(xn0 + 8);
            ra1 = *(const float2*)(xn1);
            ra3 = *(const float2*)(xn1 + 8);
            wn0 = g_wfrag[(kt + 1) * 512 + tid];
            wn1 = g_wfrag[(kt + 1) * 512 + tid + 256];
        }

        // compute: 8 n-tiles x 4 MMAs on this k16 slice
        const char* Bbase = smem + stage * WSTAGE_B;
#pragma unroll
        for (int nt = 0; nt < 8; nt++) {
            uint4 b = *(const uint4*)(Bbase + boff + nt * 512);  // nt*8 experts * 64B
            mma_f16(acc[nt], ah1[0], ah1[1], ah1[2], ah1[3], b.x, b.y);  // h1*h1
            mma_f16(acc[nt], ah1[0], ah1[1], ah1[2], ah1[3], b.z, b.w);  // h1*h2
            mma_f16(acc[nt], ah2[0], ah2[1], ah2[2], ah2[3], b.x, b.y);  // h2*h1
            mma_f16(acc[nt], ah2[0], ah2[1], ah2[2], ah2[3], b.z, b.w);  // h2*h2
        }

        // stage next W into other buffer
        if (kt + 1 < NCHUNK) {
            uint4* dst = (uint4*)(smem + (stage ^ 1) * WSTAGE_B);
            dst[tid]       = wn0;
            dst[tid + 256] = wn1;
        }
        __syncthreads();
    }

    // ---- epilogue: red[2][64][68] (k16-slice partials), unscale by 2^-18 ----
    float* red = (float*)smem;
#pragma unroll
    for (int nt = 0; nt < 8; nt++) {
        const int e = nt * 8 + 2 * tg;
        *(float2*)&red[(ksl * 64 + row0) * 68 + e] =
            make_float2(acc[nt][0] * UNSCALE, acc[nt][1] * UNSCALE);
        *(float2*)&red[(ksl * 64 + row0 + 8) * 68 + e] =
            make_float2(acc[nt][2] * UNSCALE, acc[nt][3] * UNSCALE);
    }
    __syncthreads();

    // reduce the 2 k-slices in place
    for (int i = tid; i < BM * NEXP; i += NTHREADS) {
        const int t = i >> 6, e = i & 63;
        red[t * 68 + e] = red[t * 68 + e] + red[(64 + t) * 68 + e];
    }
    __syncthreads();

    float* sc = red;   // [64][68]

    // ---- per-token softmax + top-2 ----
    if (tid < BM) {
        float v[64];
#pragma unroll
        for (int e = 0; e < NEXP; e++) v[e] = sc[tid * 68 + e];
        float mx = v[0];
#pragma unroll
        for (int e = 1; e < NEXP; e++) mx = fmaxf(mx, v[e]);
        float sum = 0.0f;
#pragma unroll
        for (int e = 0; e < NEXP; e++) { v[e] = expf(v[e] - mx); sum += v[e]; }
        float inv = 1.0f / sum;

        float v1 = -1.0f, v2 = -1.0f;
        int i1 = 0, i2 = 0;
#pragma unroll
        for (int e = 0; e < NEXP; e++) {
            float p = v[e] * inv;
            sc[tid * 68 + e] = p;
            if (p > v1) { v2 = v1; i2 = i1; v1 = p; i1 = e; }
            else if (p > v2) { v2 = p; i2 = e; }
        }
        float tot = v1 + v2 + 1e-20f;
        const int gt = tok0 + tid;
        out[2 * gt + 0] = (float)i1;
        out[2 * gt + 1] = (float)i2;
        out[2 * T_TOK + 2 * gt + 0] = v1 / tot;
        out[2 * T_TOK + 2 * gt + 1] = v2 / tot;

        atomicAdd(&cnt[i1], 1u);
        atomicAdd(&cnt[i2], 1u);
    }
    __syncthreads();

    // ---- per-expert sums -> global ----
    if (tid < NEXP) {
        float cs = 0.0f;
#pragma unroll 8
        for (int t = 0; t < BM; t++) cs += sc[t * 68 + tid];
        const int b = tok0 / SEQ;
        atomicAdd(&g_score_sum[b * NEXP + tid], cs);
        atomicAdd(&g_counts[b * NEXP + tid], cnt[tid]);
    }

    // ---- last-block finalize (aux loss) ----
    __threadfence();
    __syncthreads();
    if (tid == 0) {
        unsigned int v = atomicAdd(&g_done, 1u);
        last_flag = (v == (unsigned int)(GRID - 1));
    }
    __syncthreads();
    if (last_flag) {
        float* redf = (float*)smem;
        const int i = tid;            // 256 = NB*NEXP
        float sv = *((volatile float*)&g_score_sum[i]);
        unsigned int cv = *((volatile unsigned int*)&g_counts[i]);
        float v = (float)cv * ((float)NEXP / (float)(SEQ * 2)) * (sv / (float)SEQ);
        g_score_sum[i] = 0.0f;
        g_counts[i] = 0u;
        if (tid == 0) g_done = 0u;
        redf[i] = v;
        __syncthreads();
        for (int s = (NB * NEXP) / 2; s > 0; s >>= 1) {
            if (i < s) redf[i] += redf[i + s];
            __syncthreads();
        }
        if (i == 0) out[4 * T_TOK] = redf[0] * (0.1f / (float)NB);
    }
}

extern "C" void kernel_launch(void* const* d_in, const int* in_sizes, int n_in,
                              void* d_out, int out_size) {
    const float* X = (const float*)d_in[0];   // [4,4096,2048] f32
    const float* W = (const float*)d_in[1];   // [64,2048] f32
    float* out = (float*)d_out;

    presplit_w_kernel<<<NKB * NEXP * 4 / 256, 256>>>(W);
    cudaFuncSetAttribute(moe_gate_f16, cudaFuncAttributeMaxDynamicSharedMemorySize, SMEM_BYTES);
    moe_gate_f16<<<GRID, NTHREADS, SMEM_BYTES>>>(X, out);
}